// round 1
// baseline (speedup 1.0000x reference)
#include <cuda_runtime.h>
#include <math.h>

#define NN 80
#define PAIRS (NN * NN)          // 6400
#define MAX_ITERS 60
#define TOL 1e-3f
#define TPB 256
#define RED_BLOCKS 100           // 100 * 64 = 6400
#define PAIRS_PER_RED 64

// Scratch (allocation-free rule: __device__ globals)
__device__ float g_deltas[PAIRS * NN];        // 2 MB: per-pair delta vectors
__device__ float g_partials[RED_BLOCKS * NN]; // 32 KB: stage-1 partial sums

// Warp-per-row matvec over the 80x80 shared matrix.
// warp w handles rows w, w+8, ..., w+72 (8 warps x 10 rows).
__device__ __forceinline__ void matvec(const float* __restrict__ A,
                                       const float* __restrict__ v,
                                       float* __restrict__ w_out,
                                       int warp, int lane) {
    #pragma unroll
    for (int r = 0; r < 10; ++r) {
        int row = warp + (r << 3);
        const float* Arow = A + row * NN;
        float s = Arow[lane] * v[lane] + Arow[lane + 32] * v[lane + 32];
        if (lane < 16) s += Arow[lane + 64] * v[lane + 64];
        #pragma unroll
        for (int off = 16; off; off >>= 1)
            s += __shfl_xor_sync(0xFFFFFFFFu, s, off);
        if (lane == 0) w_out[row] = s;
    }
}

// Block-wide dot of two 80-float shared vectors; result broadcast to all threads.
__device__ __forceinline__ float block_dot(const float* __restrict__ a,
                                           const float* __restrict__ b,
                                           float* s_red, int warp, int lane) {
    __syncthreads();                  // inputs ready + protect s_red reuse
    if (warp == 0) {
        float s = a[lane] * b[lane] + a[lane + 32] * b[lane + 32];
        if (lane < 16) s += a[lane + 64] * b[lane + 64];
        #pragma unroll
        for (int off = 16; off; off >>= 1)
            s += __shfl_xor_sync(0xFFFFFFFFu, s, off);
        if (lane == 0) *s_red = s;
    }
    __syncthreads();
    return *s_red;
}

__global__ __launch_bounds__(TPB)
void power_iter_kernel(const float* __restrict__ r_zeros,
                       const float* __restrict__ r_const,
                       const float* __restrict__ t_paths,
                       const float* __restrict__ weights_t,
                       const float* __restrict__ weights_r) {
    __shared__ float A[NN * NN];   // 25.6 KB
    __shared__ float v[NN];
    __shared__ float w[NN];
    __shared__ float s_red;

    const int p    = blockIdx.x;
    const int tid  = threadIdx.x;
    const int warp = tid >> 5;
    const int lane = tid & 31;

    // ---- Build A = weights_r * r_zeros + r_const (contiguous 25.6 KB block per pair)
    const size_t base = (size_t)p * (NN * NN);
    const float4* __restrict__ rz = (const float4*)(r_zeros  + base);
    const float4* __restrict__ rc = (const float4*)(r_const  + base);
    const float4* __restrict__ wr = (const float4*)(weights_r + base);
    float4* A4 = (float4*)A;
    #pragma unroll 2
    for (int i = tid; i < (NN * NN) / 4; i += TPB) {
        float4 a = wr[i], b = rz[i], c = rc[i];
        float4 o;
        o.x = fmaf(a.x, b.x, c.x);
        o.y = fmaf(a.y, b.y, c.y);
        o.z = fmaf(a.z, b.z, c.z);
        o.w = fmaf(a.w, b.w, c.w);
        A4[i] = o;
    }
    if (tid < NN) v[tid] = 0.11180339887498949f;  // 1/sqrt(80)
    __syncthreads();

    // ---- w = A v0 ; ev = v0 . w   (matches JAX ev0 = v.(Av))
    matvec(A, v, w, warp, lane);
    float ev = block_dot(v, w, &s_red, warp, lane);

    // ---- scan body x60 with convergence break (v updated on the converging step)
    for (int it = 0; it < MAX_ITERS; ++it) {
        float n2  = block_dot(w, w, &s_red, warp, lane);
        float inv = 1.0f / sqrtf(n2);
        if (tid < NN) v[tid] = w[tid] * inv;   // v_new = Av / ||Av||
        __syncthreads();
        matvec(A, v, w, warp, lane);           // w = A v_new
        float ev_new = block_dot(v, w, &s_red, warp, lane);
        if (fabsf(ev - ev_new) < TOL) break;   // uniform branch (shared broadcast)
        ev = ev_new;
    }

    // ---- deltas[p][i] = v[i] * (T[p] / v[src])
    if (tid < NN) {
        float tval = weights_t[p] * t_paths[p];   // [n,n] row-major, linear idx p
        float coef = tval / v[p / NN];            // src = p / n
        g_deltas[(size_t)p * NN + tid] = v[tid] * coef;
    }
}

// Stage-1 reduce: block b sums pairs [b*64, b*64+64) -> partials[b][i]. Coalesced.
__global__ void reduce_stage1() {
    const int b = blockIdx.x;
    const int i = threadIdx.x;   // 0..79
    float s = 0.0f;
    const int p0 = b * PAIRS_PER_RED;
    #pragma unroll 4
    for (int k = 0; k < PAIRS_PER_RED; ++k)
        s += g_deltas[(size_t)(p0 + k) * NN + i];
    g_partials[b * NN + i] = s;
}

// Stage-2 reduce: 80 threads, fixed order over 100 partials. Deterministic.
__global__ void reduce_stage2(float* __restrict__ out) {
    const int i = threadIdx.x;   // 0..79
    float s = 0.0f;
    #pragma unroll 4
    for (int b = 0; b < RED_BLOCKS; ++b)
        s += g_partials[b * NN + i];
    out[i] = s;
}

extern "C" void kernel_launch(void* const* d_in, const int* in_sizes, int n_in,
                              void* d_out, int out_size) {
    // metadata order: 0:x (unused), 1:r_zeros, 2:r_const, 3:t_paths,
    //                 4:weights_t, 5:weights_r
    const float* r_zeros   = (const float*)d_in[1];
    const float* r_const   = (const float*)d_in[2];
    const float* t_paths   = (const float*)d_in[3];
    const float* weights_t = (const float*)d_in[4];
    const float* weights_r = (const float*)d_in[5];
    float* out = (float*)d_out;

    power_iter_kernel<<<PAIRS, TPB>>>(r_zeros, r_const, t_paths, weights_t, weights_r);
    reduce_stage1<<<RED_BLOCKS, NN>>>();
    reduce_stage2<<<1, NN>>>(out);
}

// round 2
// speedup vs baseline: 1.7420x; 1.7420x over previous
#include <cuda_runtime.h>
#include <math.h>

#define NN 80
#define PAIRS (NN * NN)          // 6400
#define MAX_ITERS 60
#define TOL 1e-3f
#define TPB 256
#define RED_BLOCKS 100           // 100 * 64 = 6400
#define PAIRS_PER_RED 64

// Scratch (allocation-free rule: __device__ globals)
__device__ float g_deltas[PAIRS * NN];        // 2 MB: per-pair delta vectors
__device__ float g_partials[RED_BLOCKS * NN]; // 32 KB: stage-1 partial sums

__global__ __launch_bounds__(TPB, 4)
void power_iter_kernel(const float* __restrict__ r_zeros,
                       const float* __restrict__ r_const,
                       const float* __restrict__ t_paths,
                       const float* __restrict__ weights_t,
                       const float* __restrict__ weights_r) {
    __shared__ float v[NN];        // current eigenvector estimate
    __shared__ float wv[NN];       // w = A v
    __shared__ float red_ww[8];    // per-warp partials of w.w
    __shared__ float red_vw[8];    // per-warp partials of v.w
    __shared__ float s_n2;         // broadcast: ||w||^2
    __shared__ float s_ev;         // broadcast: v . (A v)

    const int p    = blockIdx.x;
    const int tid  = threadIdx.x;
    const int warp = tid >> 5;
    const int lane = tid & 31;

    // ---- Build A = weights_r * r_zeros + r_const DIRECTLY INTO REGISTERS.
    // Warp w owns rows {w, w+8, ..., w+72}. Lane holds cols lane, lane+32,
    // lane+64 (lane<16 only). All loads coalesced; streaming hint (read-once).
    const size_t base = (size_t)p * (NN * NN);
    const float* __restrict__ rz = r_zeros  + base;
    const float* __restrict__ rc = r_const  + base;
    const float* __restrict__ wr = weights_r + base;

    float a0[10], a1[10], a2[10];
    #pragma unroll
    for (int r = 0; r < 10; ++r) {
        const int row = warp + (r << 3);
        const int o0  = row * NN + lane;
        const int o1  = o0 + 32;
        a0[r] = fmaf(__ldcs(wr + o0), __ldcs(rz + o0), __ldcs(rc + o0));
        a1[r] = fmaf(__ldcs(wr + o1), __ldcs(rz + o1), __ldcs(rc + o1));
        a2[r] = 0.0f;
        if (lane < 16) {
            const int o2 = o0 + 64;
            a2[r] = fmaf(__ldcs(wr + o2), __ldcs(rz + o2), __ldcs(rc + o2));
        }
    }

    if (tid < NN) v[tid] = 0.11180339887498949f;  // 1/sqrt(80)
    __syncthreads();

    // Fused matvec + dots: wv = A v ; s_n2 = wv.wv ; s_ev = v.wv
    auto mv = [&]() {
        const float vr0 = v[lane];
        const float vr1 = v[lane + 32];
        const float vr2 = (lane < 16) ? v[lane + 64] : 0.0f;
        float ww = 0.0f, vwacc = 0.0f;
        #pragma unroll
        for (int r = 0; r < 10; ++r) {
            const int row = warp + (r << 3);
            float s = a0[r] * vr0;
            s = fmaf(a1[r], vr1, s);
            s = fmaf(a2[r], vr2, s);
            #pragma unroll
            for (int off = 16; off; off >>= 1)
                s += __shfl_xor_sync(0xFFFFFFFFu, s, off);
            if (lane == 0) {
                wv[row] = s;
                ww    = fmaf(s, s, ww);
                vwacc = fmaf(v[row], s, vwacc);
            }
        }
        if (lane == 0) { red_ww[warp] = ww; red_vw[warp] = vwacc; }
        __syncthreads();
        if (tid == 0) {
            float A = 0.0f, B = 0.0f;
            #pragma unroll
            for (int k = 0; k < 8; ++k) { A += red_ww[k]; B += red_vw[k]; }
            s_n2 = A; s_ev = B;
        }
        __syncthreads();
    };

    // ---- ev0 = v0 . (A v0)   (wv = A v0 carried into the first loop body)
    mv();
    float ev = s_ev;

    // ---- scan body x60 with convergence break (v updated on converging step)
    for (int it = 0; it < MAX_ITERS; ++it) {
        const float inv = 1.0f / sqrtf(s_n2);
        if (tid < NN) v[tid] = wv[tid] * inv;    // v_new = Av / ||Av||
        __syncthreads();
        mv();                                     // wv = A v_new ; s_ev = v_new.wv
        const float ev_new = s_ev;
        if (fabsf(ev - ev_new) < TOL) break;      // uniform (shared broadcast)
        ev = ev_new;
    }

    // ---- deltas[p][i] = v[i] * (T[p] / v[src]),  src = p / n
    if (tid < NN) {
        const float tval = weights_t[p] * t_paths[p];
        const float coef = tval / v[p / NN];
        g_deltas[(size_t)p * NN + tid] = v[tid] * coef;
    }
}

// Stage-1 reduce: block b sums pairs [b*64, b*64+64) -> partials[b][i]. Coalesced.
__global__ void reduce_stage1() {
    const int b = blockIdx.x;
    const int i = threadIdx.x;   // 0..79
    float s = 0.0f;
    const int p0 = b * PAIRS_PER_RED;
    #pragma unroll 4
    for (int k = 0; k < PAIRS_PER_RED; ++k)
        s += g_deltas[(size_t)(p0 + k) * NN + i];
    g_partials[b * NN + i] = s;
}

// Stage-2 reduce: 80 threads, fixed order over 100 partials. Deterministic.
__global__ void reduce_stage2(float* __restrict__ out) {
    const int i = threadIdx.x;   // 0..79
    float s = 0.0f;
    #pragma unroll 4
    for (int b = 0; b < RED_BLOCKS; ++b)
        s += g_partials[b * NN + i];
    out[i] = s;
}

extern "C" void kernel_launch(void* const* d_in, const int* in_sizes, int n_in,
                              void* d_out, int out_size) {
    // metadata order: 0:x (unused), 1:r_zeros, 2:r_const, 3:t_paths,
    //                 4:weights_t, 5:weights_r
    const float* r_zeros   = (const float*)d_in[1];
    const float* r_const   = (const float*)d_in[2];
    const float* t_paths   = (const float*)d_in[3];
    const float* weights_t = (const float*)d_in[4];
    const float* weights_r = (const float*)d_in[5];
    float* out = (float*)d_out;

    power_iter_kernel<<<PAIRS, TPB>>>(r_zeros, r_const, t_paths, weights_t, weights_r);
    reduce_stage1<<<RED_BLOCKS, NN>>>();
    reduce_stage2<<<1, NN>>>(out);
}